// round 1
// baseline (speedup 1.0000x reference)
#include <cuda_runtime.h>

// Capsule routing layer.
// n nodes, m=32 neighbors, d=128 = k(8) capsules x dd(16).
// Mapping: 1 block (256 thr) per node; warp = capsule k, lane = neighbor m.
// z[m][k][0..15] lives in 16 registers per thread, gathered once.

static __device__ __forceinline__ float shxor(float v, int s) {
    return __shfl_xor_sync(0xffffffffu, v, s);
}

__global__ __launch_bounds__(256, 4)
void routing_kernel(const float* __restrict__ x,
                    const int*   __restrict__ nbrs,
                    const float* __restrict__ param_p,
                    const int*   __restrict__ miter_p,
                    float*       __restrict__ out,
                    int n)
{
    constexpr int K = 8, DD = 16, M = 32, DIM = 128;
    __shared__ __align__(16) float u_sh[K][DD];
    __shared__ __align__(16) float e_sh[2][M][12];   // padded rows (12 floats, 48B)

    const int node = blockIdx.x;
    const int tid  = threadIdx.x;
    const int k    = tid >> 5;    // warp id = capsule
    const int lane = tid & 31;    // lane    = neighbor index m
    const int m    = lane;

    const float param = *param_p;
    int max_iter = *miter_p;
    // defensive decode in case the scalar arrives as a float bit-pattern
    if (max_iter < 1 || max_iter > 1000) {
        float f = __int_as_float(max_iter);
        max_iter = (f >= 1.0f && f <= 1000.0f) ? (int)f : 6;
    }

    // ---- gather neighbor capsule row, L2-normalize, keep in registers ----
    float z[DD];
    const int idx = nbrs[node * M + m];
    if ((unsigned)idx < (unsigned)n) {
        const float4* src = reinterpret_cast<const float4*>(
            x + (size_t)idx * DIM + k * DD);
        #pragma unroll
        for (int q = 0; q < 4; ++q) {
            float4 t = src[q];
            z[4*q+0] = t.x; z[4*q+1] = t.y; z[4*q+2] = t.z; z[4*q+3] = t.w;
        }
        float ss = 0.f;
        #pragma unroll
        for (int d = 0; d < DD; ++d) ss = fmaf(z[d], z[d], ss);
        const float sc = __fdividef(1.0f, fmaxf(sqrtf(ss), 1e-12f));
        #pragma unroll
        for (int d = 0; d < DD; ++d) z[d] *= sc;
    } else {
        #pragma unroll
        for (int d = 0; d < DD; ++d) z[d] = 0.f;
    }

    // ---- u_before (normalized own features) at this lane's output slot ----
    // lane pair (2t, 2t+1) both own d = t
    const int dsel = (lane >> 1) & 15;
    float ub;
    {
        const float v = x[(size_t)node * DIM + k * DD + dsel];
        float s2 = v * v;
        #pragma unroll
        for (int off = 16; off; off >>= 1) s2 += shxor(s2, off);   // = 2*sum_d v^2
        const float sc = __fdividef(1.0f, fmaxf(sqrtf(0.5f * s2), 1e-12f));
        ub = v * sc;
    }

    const float w0 = param * (1.0f / (float)M) + (1.0f - param) * (1.0f / (float)K);

    for (int it = 0; it < max_iter; ++it) {
        float w;
        if (it == 0) {
            w = w0;   // p = 0 -> both softmaxes uniform
        } else {
            // ---- phase A: p = <z, u>, e = exp(p), softmax denominators ----
            const float4* up = reinterpret_cast<const float4*>(&u_sh[k][0]);
            const float4 ua = up[0], ubv = up[1], uc = up[2], ud = up[3];
            float p0 = fmaf(z[0], ua.x,  z[1] * ua.y);
            p0 = fmaf(z[2], ua.z, p0);  p0 = fmaf(z[3], ua.w, p0);
            float p1 = fmaf(z[4], ubv.x, z[5] * ubv.y);
            p1 = fmaf(z[6], ubv.z, p1); p1 = fmaf(z[7], ubv.w, p1);
            float p2 = fmaf(z[8], uc.x,  z[9] * uc.y);
            p2 = fmaf(z[10], uc.z, p2); p2 = fmaf(z[11], uc.w, p2);
            float p3 = fmaf(z[12], ud.x, z[13] * ud.y);
            p3 = fmaf(z[14], ud.z, p3); p3 = fmaf(z[15], ud.w, p3);
            const float p = (p0 + p1) + (p2 + p3);       // |p| <= 1, exp is safe
            const float e = __expf(p);

            // S_m(k): sum over neighbors = warp butterfly
            float sm = e;
            #pragma unroll
            for (int off = 16; off; off >>= 1) sm += shxor(sm, off);

            // S_k(m): sum over capsules = cross-warp via shared (double-buffered)
            e_sh[it & 1][m][k] = e;
            __syncthreads();
            const float4 ea = *reinterpret_cast<const float4*>(&e_sh[it & 1][m][0]);
            const float4 eb = *reinterpret_cast<const float4*>(&e_sh[it & 1][m][4]);
            const float sk = ((ea.x + ea.y) + (ea.z + ea.w))
                           + ((eb.x + eb.y) + (eb.z + eb.w));

            w = e * (__fdividef(param, sm) + __fdividef(1.0f - param, sk));
        }

        // ---- phase B: u[k][d] = sum_m w(m,k) * z[m][k][d]  (segmented butterfly) ----
        float v[DD];
        #pragma unroll
        for (int d = 0; d < DD; ++d) v[d] = w * z[d];

        float a8[8];
        {
            const bool hi = (lane & 16) != 0;
            #pragma unroll
            for (int j = 0; j < 8; ++j) {
                const float send = hi ? v[j] : v[j + 8];
                const float keep = hi ? v[j + 8] : v[j];
                a8[j] = keep + shxor(send, 16);
            }
        }
        float a4[4];
        {
            const bool hi = (lane & 8) != 0;
            #pragma unroll
            for (int j = 0; j < 4; ++j) {
                const float send = hi ? a8[j] : a8[j + 4];
                const float keep = hi ? a8[j + 4] : a8[j];
                a4[j] = keep + shxor(send, 8);
            }
        }
        float a2[2];
        {
            const bool hi = (lane & 4) != 0;
            #pragma unroll
            for (int j = 0; j < 2; ++j) {
                const float send = hi ? a2[0] * 0.f + a4[j] : a4[j + 2]; // see note
                const float keep = hi ? a4[j + 2] : a4[j];
                a2[j] = keep + shxor(hi ? a4[j] : a4[j + 2], 4);
                (void)send; (void)keep;
                a2[j] = (hi ? a4[j + 2] : a4[j]) + shxor(hi ? a4[j] : a4[j + 2], 4);
            }
        }
        float r;
        {
            const bool hi = (lane & 2) != 0;
            r = (hi ? a2[1] : a2[0]) + shxor(hi ? a2[0] : a2[1], 2);
        }
        r += shxor(r, 1);   // each lane now holds full sum for d = dsel

        float u = r + ub;

        if (it + 1 < max_iter) {
            // per-capsule L2 normalize (each d duplicated x2 across lane pairs)
            float s2 = u * u;
            #pragma unroll
            for (int off = 16; off; off >>= 1) s2 += shxor(s2, off);  // = 2*sum_d u^2
            const float sc = __fdividef(1.0f, fmaxf(sqrtf(0.5f * s2), 1e-12f));
            u *= sc;
            if ((lane & 1) == 0) u_sh[k][dsel] = u;
            __syncwarp();
        } else {
            if ((lane & 1) == 0)
                out[(size_t)node * DIM + k * DD + dsel] = u;
        }
    }
}

extern "C" void kernel_launch(void* const* d_in, const int* in_sizes, int n_in,
                              void* d_out, int out_size)
{
    const float* x     = (const float*)d_in[0];
    const int*   nbrs  = (const int*)d_in[1];
    const float* param = (const float*)d_in[2];
    const int*   miter = (const int*)d_in[3];
    float*       out   = (float*)d_out;

    const int n = in_sizes[0] / 128;
    routing_kernel<<<n, 256>>>(x, nbrs, param, miter, out, n);
}

// round 3
// speedup vs baseline: 1.1227x; 1.1227x over previous
#include <cuda_runtime.h>

// Capsule routing layer — redux.sync.add.s32 fixed-point version (sm_100).
// 1 block (256 thr) per node; warp = capsule k, lane = neighbor m.
// z[m][k][0..15] in 16 regs/thread; u[k][0..15] replicated across lanes
// in 2^24 fixed-point units (scale cancels in p = z·û; descaled only at store).

static __device__ __forceinline__ int redux_add_s32(int v) {
    int r;
    asm("redux.sync.add.s32 %0, %1, 0xffffffff;" : "=r"(r) : "r"(v));
    return r;
}

__global__ __launch_bounds__(256, 3)
void routing_kernel(const float* __restrict__ x,
                    const int*   __restrict__ nbrs,
                    const float* __restrict__ param_p,
                    const int*   __restrict__ miter_p,
                    float*       __restrict__ out,
                    int n)
{
    constexpr int DIM = 128, DD = 16, M = 32;
    constexpr float S24 = 16777216.0f;        // 2^24 (phase-B fixed point)
    constexpr float S22 = 4194304.0f;         // 2^22 (exp-sum fixed point)
    constexpr float IS22 = 1.0f / 4194304.0f;
    constexpr float IS24 = 1.0f / 16777216.0f;

    // row stride 36 floats: 16B-aligned rows for float4 reads
    __shared__ __align__(16) float e_sh[2][M][36];

    const int node = blockIdx.x;
    const int tid  = threadIdx.x;
    const int k    = tid >> 5;     // warp = capsule
    const int lane = tid & 31;     // lane = neighbor m

    const float param = *param_p;
    int max_iter = *miter_p;
    if (max_iter < 1 || max_iter > 1000) {            // defensive scalar decode
        float f = __int_as_float(max_iter);
        max_iter = (f >= 1.0f && f <= 1000.0f) ? (int)f : 6;
    }

    // ---- own features, normalized, pre-scaled by 2^24/32 for the redux fold ----
    float ubs[DD];
    {
        const float4* src = reinterpret_cast<const float4*>(x + (size_t)node * DIM + k * DD);
        float4 t0 = src[0], t1 = src[1], t2 = src[2], t3 = src[3];
        float v[DD] = {t0.x,t0.y,t0.z,t0.w, t1.x,t1.y,t1.z,t1.w,
                       t2.x,t2.y,t2.z,t2.w, t3.x,t3.y,t3.z,t3.w};
        float ss = 0.f;
        #pragma unroll
        for (int d = 0; d < DD; ++d) ss = fmaf(v[d], v[d], ss);
        const float sc = __fdividef(S24 / 32.0f, fmaxf(sqrtf(ss), 1e-12f));
        #pragma unroll
        for (int d = 0; d < DD; ++d) ubs[d] = v[d] * sc;
    }

    // ---- gather neighbor capsule row, L2-normalize, keep in registers ----
    float z[DD];
    {
        const int idx = nbrs[node * M + lane];
        if ((unsigned)idx < (unsigned)n) {
            const float4* src = reinterpret_cast<const float4*>(x + (size_t)idx * DIM + k * DD);
            float4 t0 = src[0], t1 = src[1], t2 = src[2], t3 = src[3];
            z[0]=t0.x; z[1]=t0.y; z[2]=t0.z; z[3]=t0.w;
            z[4]=t1.x; z[5]=t1.y; z[6]=t1.z; z[7]=t1.w;
            z[8]=t2.x; z[9]=t2.y; z[10]=t2.z; z[11]=t2.w;
            z[12]=t3.x; z[13]=t3.y; z[14]=t3.z; z[15]=t3.w;
            float ss = 0.f;
            #pragma unroll
            for (int d = 0; d < DD; ++d) ss = fmaf(z[d], z[d], ss);
            const float sc = __fdividef(1.0f, fmaxf(sqrtf(ss), 1e-12f));
            #pragma unroll
            for (int d = 0; d < DD; ++d) z[d] *= sc;
        } else {
            #pragma unroll
            for (int d = 0; d < DD; ++d) z[d] = 0.f;
        }
    }

    float uf[DD];                // u in 2^24 units, replicated across lanes
    float invn = 1.0f;           // 1/||uf|| (folds normalization AND descale into p)
    const float w0 = param * (1.0f / 32.0f) + (1.0f - param) * (1.0f / 8.0f);

    for (int it = 0; it < max_iter; ++it) {
        float w;
        if (it == 0) {
            w = w0;                              // p = 0 -> both softmaxes uniform
        } else {
            // p = <z, û> : pure intra-thread FMA on replicated uf
            float p = 0.f;
            #pragma unroll
            for (int d = 0; d < DD; ++d) p = fmaf(z[d], uf[d], p);
            p *= invn;                           // |p| <= 1, exp is safe
            const float e = __expf(p);

            // softmax-over-neighbors denominator: 1 integer redux (exact sum)
            const int   ei = __float2int_rn(e * S22);
            const float sm = (float)redux_add_s32(ei) * IS22;

            // softmax-over-capsules denominator: cross-warp via shared
            e_sh[it & 1][lane][k] = e;
            __syncthreads();
            const float4* er = reinterpret_cast<const float4*>(&e_sh[it & 1][lane][0]);
            const float4 ea = er[0], eb = er[1];
            const float sk = ((ea.x + ea.y) + (ea.z + ea.w))
                           + ((eb.x + eb.y) + (eb.z + eb.w));

            w = e * (__fdividef(param, sm) + __fdividef(1.0f - param, sk));
        }

        // uf[d] = 2^24 * (sum_m w*z[m][d] + ub[d]) via exact integer redux.
        // |w*z + ub/32| <= ~1.04 -> int <= ~1.05*2^24, 32-sum < 2^30: no overflow.
        const float ws = w * S24;
        float ss = 0.f;
        #pragma unroll
        for (int d = 0; d < DD; ++d) {
            const int vi = __float2int_rn(fmaf(ws, z[d], ubs[d]));
            uf[d] = (float)redux_add_s32(vi);
            ss = fmaf(uf[d], uf[d], ss);
        }
        invn = __frsqrt_rn(fmaxf(ss, 1e-20f));   // scale-invariant normalize
    }

    // every lane holds the full result; lane 0 of each warp writes 64B
    if (lane == 0) {
        float4* dst = reinterpret_cast<float4*>(out + (size_t)node * DIM + k * DD);
        dst[0] = make_float4(uf[0]*IS24,  uf[1]*IS24,  uf[2]*IS24,  uf[3]*IS24);
        dst[1] = make_float4(uf[4]*IS24,  uf[5]*IS24,  uf[6]*IS24,  uf[7]*IS24);
        dst[2] = make_float4(uf[8]*IS24,  uf[9]*IS24,  uf[10]*IS24, uf[11]*IS24);
        dst[3] = make_float4(uf[12]*IS24, uf[13]*IS24, uf[14]*IS24, uf[15]*IS24);
    }
}

extern "C" void kernel_launch(void* const* d_in, const int* in_sizes, int n_in,
                              void* d_out, int out_size)
{
    const float* x     = (const float*)d_in[0];
    const int*   nbrs  = (const int*)d_in[1];
    const float* param = (const float*)d_in[2];
    const int*   miter = (const int*)d_in[3];
    float*       out   = (float*)d_out;

    const int n = in_sizes[0] / 128;
    routing_kernel<<<n, 256>>>(x, nbrs, param, miter, out, n);
}

// round 4
// speedup vs baseline: 1.2481x; 1.1117x over previous
#include <cuda_runtime.h>

// Capsule routing layer — s32-redux + packed f32x2 version (sm_100).
// 1 block (256 thr) per node; warp = capsule k, lane = neighbor m.
// z/ub/u each live in 8 packed f32x2 (64-bit) registers per thread.
// u is replicated across lanes in 2^24 fixed-point units (scale cancels in
// p = z.u_hat; descaled only at the final store).

static __device__ __forceinline__ int redux_add_s32(int v) {
    int r;
    asm("redux.sync.add.s32 %0, %1, 0xffffffff;" : "=r"(r) : "r"(v));
    return r;
}
static __device__ __forceinline__ unsigned long long pack2(float lo, float hi) {
    unsigned long long r;
    asm("mov.b64 %0, {%1, %2};" : "=l"(r) : "f"(lo), "f"(hi));
    return r;
}
static __device__ __forceinline__ void unpack2(unsigned long long v, float& lo, float& hi) {
    asm("mov.b64 {%0, %1}, %2;" : "=f"(lo), "=f"(hi) : "l"(v));
}
static __device__ __forceinline__ unsigned long long fma2(
    unsigned long long a, unsigned long long b, unsigned long long c) {
    unsigned long long r;
    asm("fma.rn.f32x2 %0, %1, %2, %3;" : "=l"(r) : "l"(a), "l"(b), "l"(c));
    return r;
}
static __device__ __forceinline__ unsigned long long mul2(
    unsigned long long a, unsigned long long b) {
    unsigned long long r;
    asm("mul.rn.f32x2 %0, %1, %2;" : "=l"(r) : "l"(a), "l"(b));
    return r;
}

__global__ __launch_bounds__(256, 4)
void routing_kernel(const float* __restrict__ x,
                    const int*   __restrict__ nbrs,
                    const float* __restrict__ param_p,
                    const int*   __restrict__ miter_p,
                    float*       __restrict__ out,
                    int n)
{
    constexpr int DIM = 128, DD = 16, M = 32;
    constexpr float S24  = 16777216.0f;       // 2^24 (phase-B fixed point)
    constexpr float S22  = 4194304.0f;        // 2^22 (exp-sum fixed point)
    constexpr float IS22 = 1.0f / 4194304.0f;
    constexpr float IS24 = 1.0f / 16777216.0f;

    __shared__ __align__(16) float e_sh[2][M][36];   // padded rows, float4-readable

    const int node = blockIdx.x;
    const int tid  = threadIdx.x;
    const int k    = tid >> 5;     // warp = capsule
    const int lane = tid & 31;     // lane = neighbor m

    const float param = *param_p;
    int max_iter = *miter_p;
    if (max_iter < 1 || max_iter > 1000) {
        float f = __int_as_float(max_iter);
        max_iter = (f >= 1.0f && f <= 1000.0f) ? (int)f : 6;
    }

    // ---- own features: normalize, pre-scale by 2^24/32, keep packed ----
    unsigned long long ubp[8];
    {
        const float4* src = reinterpret_cast<const float4*>(x + (size_t)node * DIM + k * DD);
        float4 t0 = src[0], t1 = src[1], t2 = src[2], t3 = src[3];
        float v[DD] = {t0.x,t0.y,t0.z,t0.w, t1.x,t1.y,t1.z,t1.w,
                       t2.x,t2.y,t2.z,t2.w, t3.x,t3.y,t3.z,t3.w};
        float ss = 0.f;
        #pragma unroll
        for (int d = 0; d < DD; ++d) ss = fmaf(v[d], v[d], ss);
        const float sc = __fdividef(S24 / 32.0f, fmaxf(sqrtf(ss), 1e-12f));
        #pragma unroll
        for (int j = 0; j < 8; ++j) ubp[j] = pack2(v[2*j] * sc, v[2*j+1] * sc);
    }

    // ---- gather neighbor capsule row, L2-normalize, keep packed ----
    unsigned long long zp[8];
    {
        const int idx = nbrs[node * M + lane];
        float z[DD];
        if ((unsigned)idx < (unsigned)n) {
            const float4* src = reinterpret_cast<const float4*>(x + (size_t)idx * DIM + k * DD);
            float4 t0 = src[0], t1 = src[1], t2 = src[2], t3 = src[3];
            z[0]=t0.x; z[1]=t0.y; z[2]=t0.z; z[3]=t0.w;
            z[4]=t1.x; z[5]=t1.y; z[6]=t1.z; z[7]=t1.w;
            z[8]=t2.x; z[9]=t2.y; z[10]=t2.z; z[11]=t2.w;
            z[12]=t3.x; z[13]=t3.y; z[14]=t3.z; z[15]=t3.w;
            float ss = 0.f;
            #pragma unroll
            for (int d = 0; d < DD; ++d) ss = fmaf(z[d], z[d], ss);
            const float sc = __fdividef(1.0f, fmaxf(sqrtf(ss), 1e-12f));
            #pragma unroll
            for (int d = 0; d < DD; ++d) z[d] *= sc;
        } else {
            #pragma unroll
            for (int d = 0; d < DD; ++d) z[d] = 0.f;
        }
        #pragma unroll
        for (int j = 0; j < 8; ++j) zp[j] = pack2(z[2*j], z[2*j+1]);
    }

    unsigned long long up[8];    // u in 2^24 units, replicated, packed
    float invn = 1.0f;           // 1/||u_fixed|| (folds normalize + descale into p)
    const float w0 = param * (1.0f / 32.0f) + (1.0f - param) * (1.0f / 8.0f);

    for (int it = 0; it < max_iter; ++it) {
        float w;
        if (it == 0) {
            w = w0;                                  // p = 0 -> uniform softmaxes
        } else {
            // p = <z, u_hat>, packed dot product
            unsigned long long pp = 0ull;
            #pragma unroll
            for (int j = 0; j < 8; ++j) pp = fma2(zp[j], up[j], pp);
            float plo, phi; unpack2(pp, plo, phi);
            const float p = (plo + phi) * invn;      // |p| <= 1
            const float e = __expf(p);

            // softmax-over-neighbors denominator: exact integer redux
            const int   ei = __float2int_rn(e * S22);
            const float sm = (float)redux_add_s32(ei) * IS22;

            // softmax-over-capsules denominator: cross-warp via shared
            e_sh[it & 1][lane][k] = e;
            __syncthreads();
            const float4* er = reinterpret_cast<const float4*>(&e_sh[it & 1][lane][0]);
            const float4 ea = er[0], eb = er[1];
            const float sk = ((ea.x + ea.y) + (ea.z + ea.w))
                           + ((eb.x + eb.y) + (eb.z + eb.w));

            w = e * (__fdividef(param, sm) + __fdividef(1.0f - param, sk));
        }

        // u[d] = 2^24*(sum_m w*z[m][d] + ub[d]) via exact integer redux.
        // |w*z + ub/32| <= ~1.04 -> 32-sum < 2^30: no overflow.
        const float ws = w * S24;
        const unsigned long long ws2 = pack2(ws, ws);
        unsigned long long ss2 = 0ull;
        #pragma unroll
        for (int j = 0; j < 8; ++j) {
            const unsigned long long t = fma2(ws2, zp[j], ubp[j]);
            float f0, f1; unpack2(t, f0, f1);
            const float u0 = (float)redux_add_s32(__float2int_rn(f0));
            const float u1 = (float)redux_add_s32(__float2int_rn(f1));
            up[j] = pack2(u0, u1);
            ss2 = fma2(up[j], up[j], ss2);
        }
        float slo, shi; unpack2(ss2, slo, shi);
        invn = __frsqrt_rn(fmaxf(slo + shi, 1e-20f));
    }

    // every lane holds the full result; lane 0 of each warp writes 64B
    if (lane == 0) {
        float uo[DD];
        #pragma unroll
        for (int j = 0; j < 8; ++j) {
            float a, b; unpack2(up[j], a, b);
            uo[2*j] = a * IS24; uo[2*j+1] = b * IS24;
        }
        float4* dst = reinterpret_cast<float4*>(out + (size_t)node * DIM + k * DD);
        dst[0] = make_float4(uo[0],  uo[1],  uo[2],  uo[3]);
        dst[1] = make_float4(uo[4],  uo[5],  uo[6],  uo[7]);
        dst[2] = make_float4(uo[8],  uo[9],  uo[10], uo[11]);
        dst[3] = make_float4(uo[12], uo[13], uo[14], uo[15]);
    }
}

extern "C" void kernel_launch(void* const* d_in, const int* in_sizes, int n_in,
                              void* d_out, int out_size)
{
    const float* x     = (const float*)d_in[0];
    const int*   nbrs  = (const int*)d_in[1];
    const float* param = (const float*)d_in[2];
    const int*   miter = (const int*)d_in[3];
    float*       out   = (float*)d_out;

    const int n = in_sizes[0] / 128;
    routing_kernel<<<n, 256>>>(x, nbrs, param, miter, out, n);
}